// round 2
// baseline (speedup 1.0000x reference)
#include <cuda_runtime.h>
#include <math.h>

// Problem constants
#define B_  2
#define T_  2048
#define DM  1024
#define DFF 4096
#define NH  16
#define DH  64
#define MROWS (B_*T_)          // 4096

// ---------------- scratch (no allocations allowed) ----------------
__device__ float g_h   [(size_t)MROWS * DM];        // rmsnorm1 out
__device__ float g_qkv [(size_t)MROWS * 3 * DM];    // qkv
__device__ float g_y   [(size_t)MROWS * DM];        // attn out
__device__ float g_x1  [(size_t)MROWS * DM];        // x + attn
__device__ float g_h2  [(size_t)MROWS * DM];        // rmsnorm2 out
__device__ float g_gate[(size_t)MROWS * DFF];       // gate / silu*up (in place)
__device__ float g_up  [(size_t)MROWS * DFF];       // up

// ---------------- RMSNorm: one block per row, D=1024 ----------------
__global__ void __launch_bounds__(256) rmsnorm_kernel(const float* __restrict__ x,
                                                      const float* __restrict__ g,
                                                      float* __restrict__ out) {
    int row = blockIdx.x;
    const float4* xr = (const float4*)(x + (size_t)row * DM);
    float4 v = xr[threadIdx.x];
    float ss = v.x*v.x + v.y*v.y + v.z*v.z + v.w*v.w;
    #pragma unroll
    for (int o = 16; o; o >>= 1) ss += __shfl_xor_sync(0xffffffffu, ss, o);
    __shared__ float sred[8];
    int w = threadIdx.x >> 5;
    if ((threadIdx.x & 31) == 0) sred[w] = ss;
    __syncthreads();
    if (threadIdx.x < 8) {
        float t = sred[threadIdx.x];
        #pragma unroll
        for (int o = 4; o; o >>= 1) t += __shfl_xor_sync(0xffu, t, o);
        if (threadIdx.x == 0) sred[0] = t;
    }
    __syncthreads();
    float scale = rsqrtf(sred[0] * (1.0f / (float)DM) + 1e-6f);
    const float4* gr = (const float4*)g;
    float4 gv = gr[threadIdx.x];
    float4 r;
    r.x = v.x * scale * gv.x;
    r.y = v.y * scale * gv.y;
    r.z = v.z * scale * gv.z;
    r.w = v.w * scale * gv.w;
    ((float4*)(out + (size_t)row * DM))[threadIdx.x] = r;
}

// ---------------- NT SGEMM: C[M,N] = A[M,K] * B[N,K]^T (+ R) ----------------
// BM=BN=128, BK=16, 256 threads, 8x8 per-thread microtile, double-buffered smem.
// M is always 4096; N,K multiples of 128/16 -> no bounds checks.
template<bool RES>
__global__ void __launch_bounds__(256) gemm_nt(const float* __restrict__ A,
                                               const float* __restrict__ Bw,
                                               const float* __restrict__ R,
                                               float* __restrict__ C,
                                               int N, int K) {
    __shared__ float As[2][16][132];
    __shared__ float Bs[2][16][132];
    int tid = threadIdx.x;
    int bxn = blockIdx.x * 128;     // N offset
    int bym = blockIdx.y * 128;     // M offset
    int tx = tid & 15, ty = tid >> 4;

    float acc[8][8];
    #pragma unroll
    for (int i = 0; i < 8; i++)
        #pragma unroll
        for (int j = 0; j < 8; j++) acc[i][j] = 0.f;

    const float* Aptr = A + (size_t)bym * K;
    const float* Bptr = Bw + (size_t)bxn * K;
    int lrow = tid >> 2;            // 0..63
    int lc4  = (tid & 3) * 4;       // 0,4,8,12

    // prologue: load tile 0 into buffer 0
    float4 a0 = *(const float4*)(Aptr + (size_t)lrow        * K + lc4);
    float4 a1 = *(const float4*)(Aptr + (size_t)(lrow + 64) * K + lc4);
    float4 b0 = *(const float4*)(Bptr + (size_t)lrow        * K + lc4);
    float4 b1 = *(const float4*)(Bptr + (size_t)(lrow + 64) * K + lc4);
    As[0][lc4+0][lrow] = a0.x; As[0][lc4+1][lrow] = a0.y; As[0][lc4+2][lrow] = a0.z; As[0][lc4+3][lrow] = a0.w;
    As[0][lc4+0][lrow+64] = a1.x; As[0][lc4+1][lrow+64] = a1.y; As[0][lc4+2][lrow+64] = a1.z; As[0][lc4+3][lrow+64] = a1.w;
    Bs[0][lc4+0][lrow] = b0.x; Bs[0][lc4+1][lrow] = b0.y; Bs[0][lc4+2][lrow] = b0.z; Bs[0][lc4+3][lrow] = b0.w;
    Bs[0][lc4+0][lrow+64] = b1.x; Bs[0][lc4+1][lrow+64] = b1.y; Bs[0][lc4+2][lrow+64] = b1.z; Bs[0][lc4+3][lrow+64] = b1.w;
    __syncthreads();

    int buf = 0;
    for (int k0 = 16; k0 < K; k0 += 16) {
        // prefetch next tile into registers (overlaps with compute below)
        a0 = *(const float4*)(Aptr + (size_t)lrow        * K + k0 + lc4);
        a1 = *(const float4*)(Aptr + (size_t)(lrow + 64) * K + k0 + lc4);
        b0 = *(const float4*)(Bptr + (size_t)lrow        * K + k0 + lc4);
        b1 = *(const float4*)(Bptr + (size_t)(lrow + 64) * K + k0 + lc4);

        #pragma unroll
        for (int k = 0; k < 16; k++) {
            float4 av0 = *(const float4*)&As[buf][k][ty * 8];
            float4 av1 = *(const float4*)&As[buf][k][ty * 8 + 4];
            float4 bv0 = *(const float4*)&Bs[buf][k][tx * 8];
            float4 bv1 = *(const float4*)&Bs[buf][k][tx * 8 + 4];
            float a[8] = {av0.x, av0.y, av0.z, av0.w, av1.x, av1.y, av1.z, av1.w};
            float b[8] = {bv0.x, bv0.y, bv0.z, bv0.w, bv1.x, bv1.y, bv1.z, bv1.w};
            #pragma unroll
            for (int i = 0; i < 8; i++)
                #pragma unroll
                for (int j = 0; j < 8; j++)
                    acc[i][j] += a[i] * b[j];
        }

        int nb = buf ^ 1;
        As[nb][lc4+0][lrow] = a0.x; As[nb][lc4+1][lrow] = a0.y; As[nb][lc4+2][lrow] = a0.z; As[nb][lc4+3][lrow] = a0.w;
        As[nb][lc4+0][lrow+64] = a1.x; As[nb][lc4+1][lrow+64] = a1.y; As[nb][lc4+2][lrow+64] = a1.z; As[nb][lc4+3][lrow+64] = a1.w;
        Bs[nb][lc4+0][lrow] = b0.x; Bs[nb][lc4+1][lrow] = b0.y; Bs[nb][lc4+2][lrow] = b0.z; Bs[nb][lc4+3][lrow] = b0.w;
        Bs[nb][lc4+0][lrow+64] = b1.x; Bs[nb][lc4+1][lrow+64] = b1.y; Bs[nb][lc4+2][lrow+64] = b1.z; Bs[nb][lc4+3][lrow+64] = b1.w;
        __syncthreads();
        buf = nb;
    }

    // epilogue compute on last buffer
    #pragma unroll
    for (int k = 0; k < 16; k++) {
        float4 av0 = *(const float4*)&As[buf][k][ty * 8];
        float4 av1 = *(const float4*)&As[buf][k][ty * 8 + 4];
        float4 bv0 = *(const float4*)&Bs[buf][k][tx * 8];
        float4 bv1 = *(const float4*)&Bs[buf][k][tx * 8 + 4];
        float a[8] = {av0.x, av0.y, av0.z, av0.w, av1.x, av1.y, av1.z, av1.w};
        float b[8] = {bv0.x, bv0.y, bv0.z, bv0.w, bv1.x, bv1.y, bv1.z, bv1.w};
        #pragma unroll
        for (int i = 0; i < 8; i++)
            #pragma unroll
            for (int j = 0; j < 8; j++)
                acc[i][j] += a[i] * b[j];
    }

    #pragma unroll
    for (int i = 0; i < 8; i++) {
        size_t rowi = (size_t)(bym + ty * 8 + i);
        float* cp = C + rowi * N + bxn + tx * 8;
        float4 r0 = make_float4(acc[i][0], acc[i][1], acc[i][2], acc[i][3]);
        float4 r1 = make_float4(acc[i][4], acc[i][5], acc[i][6], acc[i][7]);
        if (RES) {
            const float* rp = R + rowi * N + bxn + tx * 8;
            float4 q0 = *(const float4*)(rp);
            float4 q1 = *(const float4*)(rp + 4);
            r0.x += q0.x; r0.y += q0.y; r0.z += q0.z; r0.w += q0.w;
            r1.x += q1.x; r1.y += q1.y; r1.z += q1.z; r1.w += q1.w;
        }
        *(float4*)(cp)     = r0;
        *(float4*)(cp + 4) = r1;
    }
}

// ---------------- Flash attention (causal), fp32 ----------------
// grid: (T/64 query tiles, B*H). block: 64 threads, 1 query row/thread.
__global__ void __launch_bounds__(64) flash_kernel(const float* __restrict__ qkv,
                                                   float* __restrict__ y) {
    int qt  = blockIdx.x;          // 0..31
    int bh  = blockIdx.y;          // 0..31
    int b   = bh >> 4, h = bh & 15;
    int tid = threadIdx.x;
    const float* base = qkv + (size_t)b * T_ * (3 * DM);
    int t = qt * 64 + tid;

    float q[64], o[64];
    const float* qp = base + (size_t)t * (3 * DM) + h * DH;
    #pragma unroll
    for (int d4 = 0; d4 < 16; d4++) {
        float4 v = *(const float4*)(qp + d4 * 4);
        q[d4*4+0] = v.x * 0.125f;
        q[d4*4+1] = v.y * 0.125f;
        q[d4*4+2] = v.z * 0.125f;
        q[d4*4+3] = v.w * 0.125f;
    }
    #pragma unroll
    for (int d = 0; d < 64; d++) o[d] = 0.f;
    float m = -3.0e38f, l = 0.f;

    __shared__ float Ks[64][68];
    __shared__ float Vs[64][68];

    for (int kt = 0; kt <= qt; kt++) {
        __syncthreads();
        #pragma unroll
        for (int it = 0; it < 16; it++) {
            int f = it * 64 + tid;
            int r = f >> 4;
            int c = (f & 15) * 4;
            const float* kp = base + (size_t)(kt * 64 + r) * (3 * DM) + DM + h * DH + c;
            *(float4*)&Ks[r][c] = *(const float4*)kp;
            *(float4*)&Vs[r][c] = *(const float4*)(kp + DM);
        }
        __syncthreads();

        bool diag = (kt == qt);
        #pragma unroll
        for (int cch = 0; cch < 2; cch++) {
            int j0 = cch * 32;
            float s[32];
            #pragma unroll
            for (int jj = 0; jj < 32; jj++) {
                int j = j0 + jj;
                float acc = 0.f;
                #pragma unroll
                for (int d4 = 0; d4 < 16; d4++) {
                    float4 kk = *(const float4*)&Ks[j][d4 * 4];
                    acc += q[d4*4+0]*kk.x + q[d4*4+1]*kk.y + q[d4*4+2]*kk.z + q[d4*4+3]*kk.w;
                }
                s[jj] = acc;
            }
            if (diag) {
                #pragma unroll
                for (int jj = 0; jj < 32; jj++)
                    if (j0 + jj > tid) s[jj] = -3.0e38f;
            }
            float tm = m;
            #pragma unroll
            for (int jj = 0; jj < 32; jj++) tm = fmaxf(tm, s[jj]);
            float corr = __expf(m - tm);
            m = tm;
            l *= corr;
            #pragma unroll
            for (int d = 0; d < 64; d++) o[d] *= corr;
            #pragma unroll
            for (int jj = 0; jj < 32; jj++) {
                float p = __expf(s[jj] - m);
                l += p;
                int j = j0 + jj;
                #pragma unroll
                for (int d4 = 0; d4 < 16; d4++) {
                    float4 vv = *(const float4*)&Vs[j][d4 * 4];
                    o[d4*4+0] += p * vv.x;
                    o[d4*4+1] += p * vv.y;
                    o[d4*4+2] += p * vv.z;
                    o[d4*4+3] += p * vv.w;
                }
            }
        }
    }

    float inv = 1.0f / l;
    float* yp = y + (size_t)(b * T_ + t) * DM + h * DH;
    #pragma unroll
    for (int d4 = 0; d4 < 16; d4++) {
        float4 r;
        r.x = o[d4*4+0] * inv;
        r.y = o[d4*4+1] * inv;
        r.z = o[d4*4+2] * inv;
        r.w = o[d4*4+3] * inv;
        *(float4*)(yp + d4 * 4) = r;
    }
}

// ---------------- SwiGLU elementwise: g = silu(g) * u ----------------
__global__ void __launch_bounds__(256) swiglu_kernel(float* __restrict__ g,
                                                     const float* __restrict__ u,
                                                     int n4) {
    int i = blockIdx.x * blockDim.x + threadIdx.x;
    if (i < n4) {
        float4 gv = ((float4*)g)[i];
        float4 uv = ((const float4*)u)[i];
        gv.x = gv.x / (1.f + __expf(-gv.x)) * uv.x;
        gv.y = gv.y / (1.f + __expf(-gv.y)) * uv.y;
        gv.z = gv.z / (1.f + __expf(-gv.z)) * uv.z;
        gv.w = gv.w / (1.f + __expf(-gv.w)) * uv.w;
        ((float4*)g)[i] = gv;
    }
}

// ---------------- launch ----------------
extern "C" void kernel_launch(void* const* d_in, const int* in_sizes, int n_in,
                              void* d_out, int out_size) {
    const float* x     = (const float*)d_in[0];
    const float* w_qkv = (const float*)d_in[1];
    const float* w_out = (const float*)d_in[2];
    const float* g1    = (const float*)d_in[3];
    const float* g2    = (const float*)d_in[4];
    const float* w_g   = (const float*)d_in[5];
    const float* w_u   = (const float*)d_in[6];
    const float* w_o   = (const float*)d_in[7];
    float* out = (float*)d_out;

    float *h, *qkv, *y, *x1, *h2, *gate, *up;
    cudaGetSymbolAddress((void**)&h,    g_h);
    cudaGetSymbolAddress((void**)&qkv,  g_qkv);
    cudaGetSymbolAddress((void**)&y,    g_y);
    cudaGetSymbolAddress((void**)&x1,   g_x1);
    cudaGetSymbolAddress((void**)&h2,   g_h2);
    cudaGetSymbolAddress((void**)&gate, g_gate);
    cudaGetSymbolAddress((void**)&up,   g_up);

    // attention path
    rmsnorm_kernel<<<MROWS, 256>>>(x, g1, h);
    gemm_nt<false><<<dim3(3 * DM / 128, MROWS / 128), 256>>>(h, w_qkv, nullptr, qkv, 3 * DM, DM);
    flash_kernel<<<dim3(T_ / 64, B_ * NH), 64>>>(qkv, y);
    gemm_nt<true><<<dim3(DM / 128, MROWS / 128), 256>>>(y, w_out, x, x1, DM, DM);

    // MLP path
    rmsnorm_kernel<<<MROWS, 256>>>(x1, g2, h2);
    gemm_nt<false><<<dim3(DFF / 128, MROWS / 128), 256>>>(h2, w_g, nullptr, gate, DFF, DM);
    gemm_nt<false><<<dim3(DFF / 128, MROWS / 128), 256>>>(h2, w_u, nullptr, up, DFF, DM);
    swiglu_kernel<<<(MROWS * DFF / 4 + 255) / 256, 256>>>(gate, up, MROWS * DFF / 4);
    gemm_nt<true><<<dim3(DM / 128, MROWS / 128), 256>>>(gate, w_o, x1, out, DM, DFF);
}

// round 5
// speedup vs baseline: 1.6973x; 1.6973x over previous
#include <cuda_runtime.h>
#include <cstdint>
#include <math.h>

// Problem constants
#define B_  2
#define T_  2048
#define DM  1024
#define DFF 4096
#define NH  16
#define DH  64
#define MROWS (B_*T_)          // 4096

// ---------------- scratch (no allocations allowed) ----------------
__device__ float g_h   [(size_t)MROWS * DM];
__device__ float g_qkv [(size_t)MROWS * 3 * DM];
__device__ float g_y   [(size_t)MROWS * DM];
__device__ float g_x1  [(size_t)MROWS * DM];
__device__ float g_h2  [(size_t)MROWS * DM];
__device__ float g_gate[(size_t)MROWS * DFF];
__device__ float g_up  [(size_t)MROWS * DFF];
// tf32-rounded weights
__device__ float g_wqkv[(size_t)3 * DM * DM];
__device__ float g_wout[(size_t)DM * DM];
__device__ float g_wg  [(size_t)DFF * DM];
__device__ float g_wu  [(size_t)DFF * DM];
__device__ float g_wo  [(size_t)DM * DFF];

// ---------------- helpers ----------------
__device__ __forceinline__ uint32_t smem_u32(const void* p) {
    uint32_t a;
    asm("{ .reg .u64 t; cvta.to.shared.u64 t, %1; cvt.u32.u64 %0, t; }" : "=r"(a) : "l"(p));
    return a;
}
__device__ __forceinline__ float tf32r(float x) {    // round-to-nearest tf32, as float
    uint32_t r;
    asm("cvt.rna.tf32.f32 %0, %1;" : "=r"(r) : "f"(x));
    return __uint_as_float(r);
}
#define CP16(dst, src) \
    asm volatile("cp.async.cg.shared.global [%0], [%1], 16;" :: "r"(dst), "l"(src))
#define CP_COMMIT() asm volatile("cp.async.commit_group;" ::: "memory")
#define CP_WAIT1()  asm volatile("cp.async.wait_group 1;" ::: "memory")
#define CP_WAIT0()  asm volatile("cp.async.wait_group 0;" ::: "memory")

// ---------------- weight rounding (per launch, ~20us total) ----------------
__global__ void __launch_bounds__(256) round_tf32_kernel(const float* __restrict__ in,
                                                         float* __restrict__ out, int n4) {
    int i = blockIdx.x * blockDim.x + threadIdx.x;
    if (i < n4) {
        float4 v = ((const float4*)in)[i];
        v.x = tf32r(v.x); v.y = tf32r(v.y); v.z = tf32r(v.z); v.w = tf32r(v.w);
        ((float4*)out)[i] = v;
    }
}

// ---------------- RMSNorm (emits tf32-rounded output) ----------------
__global__ void __launch_bounds__(256) rmsnorm_kernel(const float* __restrict__ x,
                                                      const float* __restrict__ g,
                                                      float* __restrict__ out) {
    int row = blockIdx.x;
    const float4* xr = (const float4*)(x + (size_t)row * DM);
    float4 v = xr[threadIdx.x];
    float ss = v.x*v.x + v.y*v.y + v.z*v.z + v.w*v.w;
    #pragma unroll
    for (int o = 16; o; o >>= 1) ss += __shfl_xor_sync(0xffffffffu, ss, o);
    __shared__ float sred[8];
    int w = threadIdx.x >> 5;
    if ((threadIdx.x & 31) == 0) sred[w] = ss;
    __syncthreads();
    if (threadIdx.x < 8) {
        float t = sred[threadIdx.x];
        #pragma unroll
        for (int o = 4; o; o >>= 1) t += __shfl_xor_sync(0xffu, t, o);
        if (threadIdx.x == 0) sred[0] = t;
    }
    __syncthreads();
    float scale = rsqrtf(sred[0] * (1.0f / (float)DM) + 1e-6f);
    const float4* gr = (const float4*)g;
    float4 gv = gr[threadIdx.x];
    float4 r;
    r.x = tf32r(v.x * scale * gv.x);
    r.y = tf32r(v.y * scale * gv.y);
    r.z = tf32r(v.z * scale * gv.z);
    r.w = tf32r(v.w * scale * gv.w);
    ((float4*)(out + (size_t)row * DM))[threadIdx.x] = r;
}

// ---------------- tf32 mma.sync NT GEMM ----------------
// C[M,N] = A[M,K] * B[N,K]^T (+ R). Inputs must already be tf32-rounded.
// CTA 128x128, BK=32, 8 warps (2x4), warp tile 64x32, m16n8k8 tf32 mma.
// cp.async double-buffered smem, padded stride 36 floats (conflict-free frags).
#define TS 4608              // floats per tile (128*36)
#define GEMM_SMEM_BYTES (4 * TS * 4)   // 2 stages * (A+B) = 73728
template<bool RES>
__global__ void __launch_bounds__(256, 2) gemm_tc(const float* __restrict__ A,
                                                  const float* __restrict__ Bw,
                                                  const float* __restrict__ R,
                                                  float* __restrict__ C,
                                                  int N, int K) {
    extern __shared__ float sm[];
    uint32_t sbase = smem_u32(sm);

    int tid = threadIdx.x;
    int lane = tid & 31, wid = tid >> 5;
    int g = lane >> 2, tg = lane & 3;
    int wm = (wid & 1) * 64, wn = (wid >> 1) * 32;
    int bxn = blockIdx.x * 128, bym = blockIdx.y * 128;

    const float* Ag = A + (size_t)bym * K;
    const float* Bg = Bw + (size_t)bxn * K;

    float c[4][4][4];
    #pragma unroll
    for (int i = 0; i < 4; i++)
        #pragma unroll
        for (int j = 0; j < 4; j++) {
            c[i][j][0] = 0.f; c[i][j][1] = 0.f; c[i][j][2] = 0.f; c[i][j][3] = 0.f;
        }

    // issue cp.async for chunk at k0 into stage
    auto issue = [&](int k0, int stage) {
        uint32_t sa = sbase + stage * 2 * TS * 4;
        uint32_t sb = sa + TS * 4;
        #pragma unroll
        for (int cc = 0; cc < 4; cc++) {
            int f = tid + 256 * cc, r = f >> 3, j = f & 7;
            uint32_t off = (uint32_t)(r * 36 + j * 4) * 4;
            CP16(sa + off, Ag + (size_t)r * K + k0 + j * 4);
            CP16(sb + off, Bg + (size_t)r * K + k0 + j * 4);
        }
        CP_COMMIT();
    };

    int NC = K >> 5;
    issue(0, 0);

    for (int i = 0; i < NC; i++) {
        if (i + 1 < NC) { issue((i + 1) << 5, (i + 1) & 1); CP_WAIT1(); }
        else            { CP_WAIT0(); }
        __syncthreads();

        const float* As = sm + (i & 1) * 2 * TS;
        const float* Bs = As + TS;
        #pragma unroll
        for (int ks = 0; ks < 4; ks++) {
            int k = ks * 8;
            uint32_t a[4][4], b[4][2];
            #pragma unroll
            for (int mt = 0; mt < 4; mt++) {
                int m = wm + mt * 16 + g;
                a[mt][0] = __float_as_uint(As[m * 36 + k + tg]);
                a[mt][1] = __float_as_uint(As[(m + 8) * 36 + k + tg]);
                a[mt][2] = __float_as_uint(As[m * 36 + k + 4 + tg]);
                a[mt][3] = __float_as_uint(As[(m + 8) * 36 + k + 4 + tg]);
            }
            #pragma unroll
            for (int nt = 0; nt < 4; nt++) {
                int n = wn + nt * 8 + g;
                b[nt][0] = __float_as_uint(Bs[n * 36 + k + tg]);
                b[nt][1] = __float_as_uint(Bs[n * 36 + k + 4 + tg]);
            }
            #pragma unroll
            for (int mt = 0; mt < 4; mt++)
                #pragma unroll
                for (int nt = 0; nt < 4; nt++) {
                    asm volatile(
                        "mma.sync.aligned.m16n8k8.row.col.f32.tf32.tf32.f32 "
                        "{%0,%1,%2,%3}, {%4,%5,%6,%7}, {%8,%9}, {%0,%1,%2,%3};"
                        : "+f"(c[mt][nt][0]), "+f"(c[mt][nt][1]),
                          "+f"(c[mt][nt][2]), "+f"(c[mt][nt][3])
                        : "r"(a[mt][0]), "r"(a[mt][1]), "r"(a[mt][2]), "r"(a[mt][3]),
                          "r"(b[nt][0]), "r"(b[nt][1]));
                }
        }
        __syncthreads();
    }

    // epilogue
    #pragma unroll
    for (int mt = 0; mt < 4; mt++) {
        int row0 = bym + wm + mt * 16 + g;
        #pragma unroll
        for (int nt = 0; nt < 4; nt++) {
            int col = bxn + wn + nt * 8 + 2 * tg;
            float2 v0 = make_float2(c[mt][nt][0], c[mt][nt][1]);
            float2 v1 = make_float2(c[mt][nt][2], c[mt][nt][3]);
            if (RES) {
                float2 q0 = *(const float2*)(R + (size_t)row0 * N + col);
                float2 q1 = *(const float2*)(R + (size_t)(row0 + 8) * N + col);
                v0.x += q0.x; v0.y += q0.y;
                v1.x += q1.x; v1.y += q1.y;
            }
            *(float2*)(C + (size_t)row0 * N + col)       = v0;
            *(float2*)(C + (size_t)(row0 + 8) * N + col) = v1;
        }
    }
}

// ---------------- Flash attention (causal), fp32; emits tf32-rounded y ----------------
__global__ void __launch_bounds__(64) flash_kernel(const float* __restrict__ qkv,
                                                   float* __restrict__ y) {
    int qt  = blockIdx.x;
    int bh  = blockIdx.y;
    int b   = bh >> 4, h = bh & 15;
    int tid = threadIdx.x;
    const float* base = qkv + (size_t)b * T_ * (3 * DM);
    int t = qt * 64 + tid;

    float q[64], o[64];
    const float* qp = base + (size_t)t * (3 * DM) + h * DH;
    #pragma unroll
    for (int d4 = 0; d4 < 16; d4++) {
        float4 v = *(const float4*)(qp + d4 * 4);
        q[d4*4+0] = v.x * 0.125f;
        q[d4*4+1] = v.y * 0.125f;
        q[d4*4+2] = v.z * 0.125f;
        q[d4*4+3] = v.w * 0.125f;
    }
    #pragma unroll
    for (int d = 0; d < 64; d++) o[d] = 0.f;
    float m = -3.0e38f, l = 0.f;

    __shared__ float Ks[64][68];
    __shared__ float Vs[64][68];

    for (int kt = 0; kt <= qt; kt++) {
        __syncthreads();
        #pragma unroll
        for (int it = 0; it < 16; it++) {
            int f = it * 64 + tid;
            int r = f >> 4;
            int cidx = (f & 15) * 4;
            const float* kp = base + (size_t)(kt * 64 + r) * (3 * DM) + DM + h * DH + cidx;
            *(float4*)&Ks[r][cidx] = *(const float4*)kp;
            *(float4*)&Vs[r][cidx] = *(const float4*)(kp + DM);
        }
        __syncthreads();

        bool diag = (kt == qt);
        #pragma unroll
        for (int cch = 0; cch < 2; cch++) {
            int j0 = cch * 32;
            float s[32];
            #pragma unroll
            for (int jj = 0; jj < 32; jj++) {
                int j = j0 + jj;
                float acc = 0.f;
                #pragma unroll
                for (int d4 = 0; d4 < 16; d4++) {
                    float4 kk = *(const float4*)&Ks[j][d4 * 4];
                    acc += q[d4*4+0]*kk.x + q[d4*4+1]*kk.y + q[d4*4+2]*kk.z + q[d4*4+3]*kk.w;
                }
                s[jj] = acc;
            }
            if (diag) {
                #pragma unroll
                for (int jj = 0; jj < 32; jj++)
                    if (j0 + jj > tid) s[jj] = -3.0e38f;
            }
            float tm = m;
            #pragma unroll
            for (int jj = 0; jj < 32; jj++) tm = fmaxf(tm, s[jj]);
            float corr = __expf(m - tm);
            m = tm;
            l *= corr;
            #pragma unroll
            for (int d = 0; d < 64; d++) o[d] *= corr;
            #pragma unroll
            for (int jj = 0; jj < 32; jj++) {
                float p = __expf(s[jj] - m);
                l += p;
                int j = j0 + jj;
                #pragma unroll
                for (int d4 = 0; d4 < 16; d4++) {
                    float4 vv = *(const float4*)&Vs[j][d4 * 4];
                    o[d4*4+0] += p * vv.x;
                    o[d4*4+1] += p * vv.y;
                    o[d4*4+2] += p * vv.z;
                    o[d4*4+3] += p * vv.w;
                }
            }
        }
    }

    float inv = 1.0f / l;
    float* yp = y + (size_t)(b * T_ + t) * DM + h * DH;
    #pragma unroll
    for (int d4 = 0; d4 < 16; d4++) {
        float4 r;
        r.x = tf32r(o[d4*4+0] * inv);
        r.y = tf32r(o[d4*4+1] * inv);
        r.z = tf32r(o[d4*4+2] * inv);
        r.w = tf32r(o[d4*4+3] * inv);
        *(float4*)(yp + d4 * 4) = r;
    }
}

// ---------------- SwiGLU elementwise (emits tf32-rounded gate) ----------------
__global__ void __launch_bounds__(256) swiglu_kernel(float* __restrict__ g,
                                                     const float* __restrict__ u,
                                                     int n4) {
    int i = blockIdx.x * blockDim.x + threadIdx.x;
    if (i < n4) {
        float4 gv = ((float4*)g)[i];
        float4 uv = ((const float4*)u)[i];
        gv.x = tf32r(gv.x / (1.f + __expf(-gv.x)) * uv.x);
        gv.y = tf32r(gv.y / (1.f + __expf(-gv.y)) * uv.y);
        gv.z = tf32r(gv.z / (1.f + __expf(-gv.z)) * uv.z);
        gv.w = tf32r(gv.w / (1.f + __expf(-gv.w)) * uv.w);
        ((float4*)g)[i] = gv;
    }
}

// ---------------- launch ----------------
extern "C" void kernel_launch(void* const* d_in, const int* in_sizes, int n_in,
                              void* d_out, int out_size) {
    const float* x     = (const float*)d_in[0];
    const float* w_qkv = (const float*)d_in[1];
    const float* w_out = (const float*)d_in[2];
    const float* g1    = (const float*)d_in[3];
    const float* g2    = (const float*)d_in[4];
    const float* w_g   = (const float*)d_in[5];
    const float* w_u   = (const float*)d_in[6];
    const float* w_o   = (const float*)d_in[7];
    float* out = (float*)d_out;

    float *h, *qkv, *y, *x1, *h2, *gate, *up;
    float *wqkv, *wout, *wg, *wu, *wo;
    cudaGetSymbolAddress((void**)&h,    g_h);
    cudaGetSymbolAddress((void**)&qkv,  g_qkv);
    cudaGetSymbolAddress((void**)&y,    g_y);
    cudaGetSymbolAddress((void**)&x1,   g_x1);
    cudaGetSymbolAddress((void**)&h2,   g_h2);
    cudaGetSymbolAddress((void**)&gate, g_gate);
    cudaGetSymbolAddress((void**)&up,   g_up);
    cudaGetSymbolAddress((void**)&wqkv, g_wqkv);
    cudaGetSymbolAddress((void**)&wout, g_wout);
    cudaGetSymbolAddress((void**)&wg,   g_wg);
    cudaGetSymbolAddress((void**)&wu,   g_wu);
    cudaGetSymbolAddress((void**)&wo,   g_wo);

    // idempotent, deterministic, non-stream host calls (no static guard per rules)
    cudaFuncSetAttribute(gemm_tc<false>, cudaFuncAttributeMaxDynamicSharedMemorySize, GEMM_SMEM_BYTES);
    cudaFuncSetAttribute(gemm_tc<true>,  cudaFuncAttributeMaxDynamicSharedMemorySize, GEMM_SMEM_BYTES);

    // round weights to tf32 (deterministic & cheap)
    round_tf32_kernel<<<3 * DM * DM / 1024, 256>>>(w_qkv, wqkv, 3 * DM * DM / 4);
    round_tf32_kernel<<<DM * DM / 1024, 256>>>(w_out, wout, DM * DM / 4);
    round_tf32_kernel<<<DFF * DM / 1024, 256>>>(w_g, wg, DFF * DM / 4);
    round_tf32_kernel<<<DFF * DM / 1024, 256>>>(w_u, wu, DFF * DM / 4);
    round_tf32_kernel<<<DM * DFF / 1024, 256>>>(w_o, wo, DM * DFF / 4);

    // attention path
    rmsnorm_kernel<<<MROWS, 256>>>(x, g1, h);
    gemm_tc<false><<<dim3(3 * DM / 128, MROWS / 128), 256, GEMM_SMEM_BYTES>>>(h, wqkv, nullptr, qkv, 3 * DM, DM);
    flash_kernel<<<dim3(T_ / 64, B_ * NH), 64>>>(qkv, y);
    gemm_tc<true><<<dim3(DM / 128, MROWS / 128), 256, GEMM_SMEM_BYTES>>>(y, wout, x, x1, DM, DM);

    // MLP path
    rmsnorm_kernel<<<MROWS, 256>>>(x1, g2, h2);
    gemm_tc<false><<<dim3(DFF / 128, MROWS / 128), 256, GEMM_SMEM_BYTES>>>(h2, wg, nullptr, gate, DFF, DM);
    gemm_tc<false><<<dim3(DFF / 128, MROWS / 128), 256, GEMM_SMEM_BYTES>>>(h2, wu, nullptr, up, DFF, DM);
    swiglu_kernel<<<(MROWS * DFF / 4 + 255) / 256, 256>>>(gate, up, MROWS * DFF / 4);
    gemm_tc<true><<<dim3(DM / 128, MROWS / 128), 256, GEMM_SMEM_BYTES>>>(gate, wo, x1, out, DM, DFF);
}

// round 6
// speedup vs baseline: 4.1650x; 2.4538x over previous
#include <cuda_runtime.h>
#include <cstdint>
#include <math.h>

// Problem constants
#define B_  2
#define T_  2048
#define DM  1024
#define DFF 4096
#define NH  16
#define DH  64
#define MROWS (B_*T_)          // 4096

// ---------------- scratch (no allocations allowed) ----------------
__device__ float g_h   [(size_t)MROWS * DM];
__device__ float g_qkv [(size_t)MROWS * 3 * DM];
__device__ float g_y   [(size_t)MROWS * DM];
__device__ float g_x1  [(size_t)MROWS * DM];
__device__ float g_h2  [(size_t)MROWS * DM];
__device__ float g_gate[(size_t)MROWS * DFF];
__device__ float g_up  [(size_t)MROWS * DFF];
// tf32-rounded weights
__device__ float g_wqkv[(size_t)3 * DM * DM];
__device__ float g_wout[(size_t)DM * DM];
__device__ float g_wg  [(size_t)DFF * DM];
__device__ float g_wu  [(size_t)DFF * DM];
__device__ float g_wo  [(size_t)DM * DFF];

// ---------------- helpers ----------------
__device__ __forceinline__ uint32_t smem_u32(const void* p) {
    uint32_t a;
    asm("{ .reg .u64 t; cvta.to.shared.u64 t, %1; cvt.u32.u64 %0, t; }" : "=r"(a) : "l"(p));
    return a;
}
__device__ __forceinline__ float tf32r(float x) {    // round-to-nearest tf32, as float
    uint32_t r;
    asm("cvt.rna.tf32.f32 %0, %1;" : "=r"(r) : "f"(x));
    return __uint_as_float(r);
}
#define CP16(dst, src) \
    asm volatile("cp.async.cg.shared.global [%0], [%1], 16;" :: "r"(dst), "l"(src))
#define CP_COMMIT() asm volatile("cp.async.commit_group;" ::: "memory")
#define CP_WAIT1()  asm volatile("cp.async.wait_group 1;" ::: "memory")
#define CP_WAIT0()  asm volatile("cp.async.wait_group 0;" ::: "memory")

#define MMA_TF32(c, a, b0, b1) \
    asm volatile( \
        "mma.sync.aligned.m16n8k8.row.col.f32.tf32.tf32.f32 " \
        "{%0,%1,%2,%3}, {%4,%5,%6,%7}, {%8,%9}, {%0,%1,%2,%3};" \
        : "+f"((c)[0]), "+f"((c)[1]), "+f"((c)[2]), "+f"((c)[3]) \
        : "r"((a)[0]), "r"((a)[1]), "r"((a)[2]), "r"((a)[3]), \
          "r"(b0), "r"(b1))

// ---------------- weight rounding ----------------
__global__ void __launch_bounds__(256) round_tf32_kernel(const float* __restrict__ in,
                                                         float* __restrict__ out, int n4) {
    int i = blockIdx.x * blockDim.x + threadIdx.x;
    if (i < n4) {
        float4 v = ((const float4*)in)[i];
        v.x = tf32r(v.x); v.y = tf32r(v.y); v.z = tf32r(v.z); v.w = tf32r(v.w);
        ((float4*)out)[i] = v;
    }
}

// ---------------- RMSNorm (emits tf32-rounded output) ----------------
__global__ void __launch_bounds__(256) rmsnorm_kernel(const float* __restrict__ x,
                                                      const float* __restrict__ g,
                                                      float* __restrict__ out) {
    int row = blockIdx.x;
    const float4* xr = (const float4*)(x + (size_t)row * DM);
    float4 v = xr[threadIdx.x];
    float ss = v.x*v.x + v.y*v.y + v.z*v.z + v.w*v.w;
    #pragma unroll
    for (int o = 16; o; o >>= 1) ss += __shfl_xor_sync(0xffffffffu, ss, o);
    __shared__ float sred[8];
    int w = threadIdx.x >> 5;
    if ((threadIdx.x & 31) == 0) sred[w] = ss;
    __syncthreads();
    if (threadIdx.x < 8) {
        float t = sred[threadIdx.x];
        #pragma unroll
        for (int o = 4; o; o >>= 1) t += __shfl_xor_sync(0xffu, t, o);
        if (threadIdx.x == 0) sred[0] = t;
    }
    __syncthreads();
    float scale = rsqrtf(sred[0] * (1.0f / (float)DM) + 1e-6f);
    const float4* gr = (const float4*)g;
    float4 gv = gr[threadIdx.x];
    float4 r;
    r.x = tf32r(v.x * scale * gv.x);
    r.y = tf32r(v.y * scale * gv.y);
    r.z = tf32r(v.z * scale * gv.z);
    r.w = tf32r(v.w * scale * gv.w);
    ((float4*)(out + (size_t)row * DM))[threadIdx.x] = r;
}

// ---------------- tf32 mma.sync NT GEMM (unchanged from R5, proven) ----------------
#define TS 4608              // floats per tile (128*36)
#define GEMM_SMEM_BYTES (4 * TS * 4)   // 73728
template<bool RES>
__global__ void __launch_bounds__(256, 2) gemm_tc(const float* __restrict__ A,
                                                  const float* __restrict__ Bw,
                                                  const float* __restrict__ R,
                                                  float* __restrict__ C,
                                                  int N, int K) {
    extern __shared__ float sm[];
    uint32_t sbase = smem_u32(sm);

    int tid = threadIdx.x;
    int lane = tid & 31, wid = tid >> 5;
    int g = lane >> 2, tg = lane & 3;
    int wm = (wid & 1) * 64, wn = (wid >> 1) * 32;
    int bxn = blockIdx.x * 128, bym = blockIdx.y * 128;

    const float* Ag = A + (size_t)bym * K;
    const float* Bg = Bw + (size_t)bxn * K;

    float c[4][4][4];
    #pragma unroll
    for (int i = 0; i < 4; i++)
        #pragma unroll
        for (int j = 0; j < 4; j++) {
            c[i][j][0] = 0.f; c[i][j][1] = 0.f; c[i][j][2] = 0.f; c[i][j][3] = 0.f;
        }

    auto issue = [&](int k0, int stage) {
        uint32_t sa = sbase + stage * 2 * TS * 4;
        uint32_t sb = sa + TS * 4;
        #pragma unroll
        for (int cc = 0; cc < 4; cc++) {
            int f = tid + 256 * cc, r = f >> 3, j = f & 7;
            uint32_t off = (uint32_t)(r * 36 + j * 4) * 4;
            CP16(sa + off, Ag + (size_t)r * K + k0 + j * 4);
            CP16(sb + off, Bg + (size_t)r * K + k0 + j * 4);
        }
        CP_COMMIT();
    };

    int NC = K >> 5;
    issue(0, 0);

    for (int i = 0; i < NC; i++) {
        if (i + 1 < NC) { issue((i + 1) << 5, (i + 1) & 1); CP_WAIT1(); }
        else            { CP_WAIT0(); }
        __syncthreads();

        const float* As = sm + (i & 1) * 2 * TS;
        const float* Bs = As + TS;
        #pragma unroll
        for (int ks = 0; ks < 4; ks++) {
            int k = ks * 8;
            uint32_t a[4][4], b[4][2];
            #pragma unroll
            for (int mt = 0; mt < 4; mt++) {
                int m = wm + mt * 16 + g;
                a[mt][0] = __float_as_uint(As[m * 36 + k + tg]);
                a[mt][1] = __float_as_uint(As[(m + 8) * 36 + k + tg]);
                a[mt][2] = __float_as_uint(As[m * 36 + k + 4 + tg]);
                a[mt][3] = __float_as_uint(As[(m + 8) * 36 + k + 4 + tg]);
            }
            #pragma unroll
            for (int nt = 0; nt < 4; nt++) {
                int n = wn + nt * 8 + g;
                b[nt][0] = __float_as_uint(Bs[n * 36 + k + tg]);
                b[nt][1] = __float_as_uint(Bs[n * 36 + k + 4 + tg]);
            }
            #pragma unroll
            for (int mt = 0; mt < 4; mt++)
                #pragma unroll
                for (int nt = 0; nt < 4; nt++)
                    MMA_TF32(c[mt][nt], a[mt], b[nt][0], b[nt][1]);
        }
        __syncthreads();
    }

    #pragma unroll
    for (int mt = 0; mt < 4; mt++) {
        int row0 = bym + wm + mt * 16 + g;
        #pragma unroll
        for (int nt = 0; nt < 4; nt++) {
            int col = bxn + wn + nt * 8 + 2 * tg;
            float2 v0 = make_float2(c[mt][nt][0], c[mt][nt][1]);
            float2 v1 = make_float2(c[mt][nt][2], c[mt][nt][3]);
            if (RES) {
                float2 q0 = *(const float2*)(R + (size_t)row0 * N + col);
                float2 q1 = *(const float2*)(R + (size_t)(row0 + 8) * N + col);
                v0.x += q0.x; v0.y += q0.y;
                v1.x += q1.x; v1.y += q1.y;
            }
            *(float2*)(C + (size_t)row0 * N + col)       = v0;
            *(float2*)(C + (size_t)(row0 + 8) * N + col) = v1;
        }
    }
}

// ---------------- Tensor-core flash attention (causal, tf32 mma) ----------------
// grid (T/64, B*NH), 128 threads (4 warps). Warp w owns query rows wm..wm+15.
// S = Q@K^T and O = P@V on m16n8k8 tf32 mma; fp32 online softmax in registers.
// P round-trips through the K smem buffer (K is dead after S).
#define KS_STRIDE 68
#define VS_STRIDE 72
__global__ void __launch_bounds__(128) flash_tc(const float* __restrict__ qkv,
                                                float* __restrict__ y) {
    int qt  = (int)(gridDim.x - 1) - (int)blockIdx.x;   // longest blocks first
    int bh  = blockIdx.y;
    int b   = bh >> 4, h = bh & 15;
    int tid = threadIdx.x, lane = tid & 31, wid = tid >> 5;
    int g = lane >> 2, tg = lane & 3;
    int wm = wid * 16;
    const float* base = qkv + (size_t)b * T_ * (3 * DM);

    __shared__ float Ks[64 * KS_STRIDE];
    __shared__ float Vs[64 * VS_STRIDE];

    // stage Q tile into Ks, build A-fragments (scaled + tf32-rounded)
    for (int it = tid; it < 64 * 16; it += 128) {
        int r = it >> 4, c4 = (it & 15) * 4;
        float4 v = *(const float4*)(base + (size_t)(qt * 64 + r) * (3 * DM) + h * DH + c4);
        Ks[r * KS_STRIDE + c4 + 0] = tf32r(v.x * 0.125f);
        Ks[r * KS_STRIDE + c4 + 1] = tf32r(v.y * 0.125f);
        Ks[r * KS_STRIDE + c4 + 2] = tf32r(v.z * 0.125f);
        Ks[r * KS_STRIDE + c4 + 3] = tf32r(v.w * 0.125f);
    }
    __syncthreads();
    uint32_t qa[8][4];
    #pragma unroll
    for (int ks = 0; ks < 8; ks++) {
        qa[ks][0] = __float_as_uint(Ks[(wm + g) * KS_STRIDE + ks * 8 + tg]);
        qa[ks][1] = __float_as_uint(Ks[(wm + g + 8) * KS_STRIDE + ks * 8 + tg]);
        qa[ks][2] = __float_as_uint(Ks[(wm + g) * KS_STRIDE + ks * 8 + tg + 4]);
        qa[ks][3] = __float_as_uint(Ks[(wm + g + 8) * KS_STRIDE + ks * 8 + tg + 4]);
    }

    float o[8][4];
    #pragma unroll
    for (int nt = 0; nt < 8; nt++) { o[nt][0] = 0.f; o[nt][1] = 0.f; o[nt][2] = 0.f; o[nt][3] = 0.f; }
    float m0 = -3.0e38f, m1 = -3.0e38f, l0 = 0.f, l1 = 0.f;

    for (int kt = 0; kt <= qt; kt++) {
        __syncthreads();                 // prior tile's Vs + P(in Ks) fully consumed
        for (int it = tid; it < 64 * 16; it += 128) {
            int r = it >> 4, c4 = (it & 15) * 4;
            const float* kp = base + (size_t)(kt * 64 + r) * (3 * DM) + DM + h * DH + c4;
            float4 kv = *(const float4*)kp;
            float4 vv = *(const float4*)(kp + DM);
            Ks[r * KS_STRIDE + c4 + 0] = tf32r(kv.x);
            Ks[r * KS_STRIDE + c4 + 1] = tf32r(kv.y);
            Ks[r * KS_STRIDE + c4 + 2] = tf32r(kv.z);
            Ks[r * KS_STRIDE + c4 + 3] = tf32r(kv.w);
            Vs[r * VS_STRIDE + c4 + 0] = tf32r(vv.x);
            Vs[r * VS_STRIDE + c4 + 1] = tf32r(vv.y);
            Vs[r * VS_STRIDE + c4 + 2] = tf32r(vv.z);
            Vs[r * VS_STRIDE + c4 + 3] = tf32r(vv.w);
        }
        __syncthreads();

        // S = Q @ K^T : n-dim = keys
        float s[8][4];
        #pragma unroll
        for (int nt = 0; nt < 8; nt++) { s[nt][0] = 0.f; s[nt][1] = 0.f; s[nt][2] = 0.f; s[nt][3] = 0.f; }
        #pragma unroll
        for (int ks = 0; ks < 8; ks++) {
            #pragma unroll
            for (int nt = 0; nt < 8; nt++) {
                uint32_t b0 = __float_as_uint(Ks[(nt * 8 + g) * KS_STRIDE + ks * 8 + tg]);
                uint32_t b1 = __float_as_uint(Ks[(nt * 8 + g) * KS_STRIDE + ks * 8 + tg + 4]);
                MMA_TF32(s[nt], qa[ks], b0, b1);
            }
        }
        __syncthreads();                 // all warps done reading Ks -> safe to overwrite with P

        if (kt == qt) {                  // causal mask within diagonal tile
            #pragma unroll
            for (int nt = 0; nt < 8; nt++) {
                int j0 = nt * 8 + 2 * tg, j1 = j0 + 1;
                int i0 = wm + g, i1 = wm + g + 8;
                if (j0 > i0) s[nt][0] = -3.0e38f;
                if (j1 > i0) s[nt][1] = -3.0e38f;
                if (j0 > i1) s[nt][2] = -3.0e38f;
                if (j1 > i1) s[nt][3] = -3.0e38f;
            }
        }
        float tm0 = m0, tm1 = m1;
        #pragma unroll
        for (int nt = 0; nt < 8; nt++) {
            tm0 = fmaxf(tm0, fmaxf(s[nt][0], s[nt][1]));
            tm1 = fmaxf(tm1, fmaxf(s[nt][2], s[nt][3]));
        }
        tm0 = fmaxf(tm0, __shfl_xor_sync(0xffffffffu, tm0, 1));
        tm0 = fmaxf(tm0, __shfl_xor_sync(0xffffffffu, tm0, 2));
        tm1 = fmaxf(tm1, __shfl_xor_sync(0xffffffffu, tm1, 1));
        tm1 = fmaxf(tm1, __shfl_xor_sync(0xffffffffu, tm1, 2));
        float corr0 = __expf(m0 - tm0), corr1 = __expf(m1 - tm1);
        m0 = tm0; m1 = tm1;
        l0 *= corr0; l1 *= corr1;
        #pragma unroll
        for (int nt = 0; nt < 8; nt++) {
            o[nt][0] *= corr0; o[nt][1] *= corr0;
            o[nt][2] *= corr1; o[nt][3] *= corr1;
        }
        #pragma unroll
        for (int nt = 0; nt < 8; nt++) {
            float p00 = __expf(s[nt][0] - m0), p01 = __expf(s[nt][1] - m0);
            float p10 = __expf(s[nt][2] - m1), p11 = __expf(s[nt][3] - m1);
            l0 += p00 + p01; l1 += p10 + p11;
            *(float2*)&Ks[(wm + g) * KS_STRIDE + nt * 8 + 2 * tg]     = make_float2(tf32r(p00), tf32r(p01));
            *(float2*)&Ks[(wm + g + 8) * KS_STRIDE + nt * 8 + 2 * tg] = make_float2(tf32r(p10), tf32r(p11));
        }
        __syncwarp();                    // per-warp region: warp-local RAW only

        // O += P @ V : k-dim = keys, n-dim = head dims
        #pragma unroll
        for (int ks = 0; ks < 8; ks++) {
            uint32_t pa[4];
            pa[0] = __float_as_uint(Ks[(wm + g) * KS_STRIDE + ks * 8 + tg]);
            pa[1] = __float_as_uint(Ks[(wm + g + 8) * KS_STRIDE + ks * 8 + tg]);
            pa[2] = __float_as_uint(Ks[(wm + g) * KS_STRIDE + ks * 8 + tg + 4]);
            pa[3] = __float_as_uint(Ks[(wm + g + 8) * KS_STRIDE + ks * 8 + tg + 4]);
            #pragma unroll
            for (int nt = 0; nt < 8; nt++) {
                uint32_t b0 = __float_as_uint(Vs[(ks * 8 + tg) * VS_STRIDE + nt * 8 + g]);
                uint32_t b1 = __float_as_uint(Vs[(ks * 8 + tg + 4) * VS_STRIDE + nt * 8 + g]);
                MMA_TF32(o[nt], pa, b0, b1);
            }
        }
    }

    l0 += __shfl_xor_sync(0xffffffffu, l0, 1);
    l0 += __shfl_xor_sync(0xffffffffu, l0, 2);
    l1 += __shfl_xor_sync(0xffffffffu, l1, 1);
    l1 += __shfl_xor_sync(0xffffffffu, l1, 2);
    float inv0 = 1.0f / l0, inv1 = 1.0f / l1;

    size_t row0 = (size_t)(b * T_ + qt * 64 + wm + g);
    #pragma unroll
    for (int nt = 0; nt < 8; nt++) {
        int col = h * DH + nt * 8 + 2 * tg;
        *(float2*)(y + row0 * DM + col) =
            make_float2(tf32r(o[nt][0] * inv0), tf32r(o[nt][1] * inv0));
        *(float2*)(y + (row0 + 8) * DM + col) =
            make_float2(tf32r(o[nt][2] * inv1), tf32r(o[nt][3] * inv1));
    }
}

// ---------------- SwiGLU elementwise (emits tf32-rounded gate) ----------------
__global__ void __launch_bounds__(256) swiglu_kernel(float* __restrict__ g,
                                                     const float* __restrict__ u,
                                                     int n4) {
    int i = blockIdx.x * blockDim.x + threadIdx.x;
    if (i < n4) {
        float4 gv = ((float4*)g)[i];
        float4 uv = ((const float4*)u)[i];
        gv.x = tf32r(gv.x / (1.f + __expf(-gv.x)) * uv.x);
        gv.y = tf32r(gv.y / (1.f + __expf(-gv.y)) * uv.y);
        gv.z = tf32r(gv.z / (1.f + __expf(-gv.z)) * uv.z);
        gv.w = tf32r(gv.w / (1.f + __expf(-gv.w)) * uv.w);
        ((float4*)g)[i] = gv;
    }
}

// ---------------- launch ----------------
extern "C" void kernel_launch(void* const* d_in, const int* in_sizes, int n_in,
                              void* d_out, int out_size) {
    const float* x     = (const float*)d_in[0];
    const float* w_qkv = (const float*)d_in[1];
    const float* w_out = (const float*)d_in[2];
    const float* g1    = (const float*)d_in[3];
    const float* g2    = (const float*)d_in[4];
    const float* w_g   = (const float*)d_in[5];
    const float* w_u   = (const float*)d_in[6];
    const float* w_o   = (const float*)d_in[7];
    float* out = (float*)d_out;

    float *h, *qkv, *y, *x1, *h2, *gate, *up;
    float *wqkv, *wout, *wg, *wu, *wo;
    cudaGetSymbolAddress((void**)&h,    g_h);
    cudaGetSymbolAddress((void**)&qkv,  g_qkv);
    cudaGetSymbolAddress((void**)&y,    g_y);
    cudaGetSymbolAddress((void**)&x1,   g_x1);
    cudaGetSymbolAddress((void**)&h2,   g_h2);
    cudaGetSymbolAddress((void**)&gate, g_gate);
    cudaGetSymbolAddress((void**)&up,   g_up);
    cudaGetSymbolAddress((void**)&wqkv, g_wqkv);
    cudaGetSymbolAddress((void**)&wout, g_wout);
    cudaGetSymbolAddress((void**)&wg,   g_wg);
    cudaGetSymbolAddress((void**)&wu,   g_wu);
    cudaGetSymbolAddress((void**)&wo,   g_wo);

    cudaFuncSetAttribute(gemm_tc<false>, cudaFuncAttributeMaxDynamicSharedMemorySize, GEMM_SMEM_BYTES);
    cudaFuncSetAttribute(gemm_tc<true>,  cudaFuncAttributeMaxDynamicSharedMemorySize, GEMM_SMEM_BYTES);

    round_tf32_kernel<<<3 * DM * DM / 1024, 256>>>(w_qkv, wqkv, 3 * DM * DM / 4);
    round_tf32_kernel<<<DM * DM / 1024, 256>>>(w_out, wout, DM * DM / 4);
    round_tf32_kernel<<<DFF * DM / 1024, 256>>>(w_g, wg, DFF * DM / 4);
    round_tf32_kernel<<<DFF * DM / 1024, 256>>>(w_u, wu, DFF * DM / 4);
    round_tf32_kernel<<<DM * DFF / 1024, 256>>>(w_o, wo, DM * DFF / 4);

    // attention path
    rmsnorm_kernel<<<MROWS, 256>>>(x, g1, h);
    gemm_tc<false><<<dim3(3 * DM / 128, MROWS / 128), 256, GEMM_SMEM_BYTES>>>(h, wqkv, nullptr, qkv, 3 * DM, DM);
    flash_tc<<<dim3(T_ / 64, B_ * NH), 128>>>(qkv, y);
    gemm_tc<true><<<dim3(DM / 128, MROWS / 128), 256, GEMM_SMEM_BYTES>>>(y, wout, x, x1, DM, DM);

    // MLP path
    rmsnorm_kernel<<<MROWS, 256>>>(x1, g2, h2);
    gemm_tc<false><<<dim3(DFF / 128, MROWS / 128), 256, GEMM_SMEM_BYTES>>>(h2, wg, nullptr, gate, DFF, DM);
    gemm_tc<false><<<dim3(DFF / 128, MROWS / 128), 256, GEMM_SMEM_BYTES>>>(h2, wu, nullptr, up, DFF, DM);
    swiglu_kernel<<<(MROWS * DFF / 4 + 255) / 256, 256>>>(gate, up, MROWS * DFF / 4);
    gemm_tc<true><<<dim3(DM / 128, MROWS / 128), 256, GEMM_SMEM_BYTES>>>(gate, wo, x1, out, DM, DFF);
}